// round 9
// baseline (speedup 1.0000x reference)
#include <cuda_runtime.h>
#include <math.h>
#include <stdint.h>

#define VSZ   50000
#define EDIM  384
#define HDIM  256
#define NB    64
#define TDOC  1024
#define TQRY  32
#define G3H   768
#define HH    512
#define NROW_DOC (NB*TDOC)
#define NROW_QRY (NB*TQRY)

// ---------------- global scratch ----------------
__device__ float g_xw_doc[(size_t)NB*TDOC*1536];
__device__ float g_xw_qry[(size_t)NB*TQRY*1536];
__device__ float g_doc_h[(size_t)NB*TDOC*HH];
__device__ float g_qry_h[(size_t)NB*TQRY*HH];
__device__ float g_Wt[2*HDIM*G3H];
__device__ float g_scores[(size_t)NB*TDOC*TQRY];
__device__ float g_s[NB*TDOC];
__device__ float g_word[(size_t)NB*VSZ];

// ---------------- K0: transpose Whh into k-major float4 chunks ----------
__global__ void prep_wt(const float* __restrict__ Whh_f,
                        const float* __restrict__ Whh_b)
{
    int idx = blockIdx.x * blockDim.x + threadIdx.x;
    if (idx >= 2*HDIM*G3H) return;
    int dir = idx / (HDIM*G3H);
    int rem = idx - dir*(HDIM*G3H);
    int k = rem / G3H;
    int j = rem - k*G3H;
    const float* W = dir ? Whh_b : Whh_f;
    g_Wt[((size_t)(dir*64 + (k>>2))*G3H + j)*4 + (k&3)] = W[(size_t)j*HDIM + k];
}

// ---------------- K1: xw = emb[tok] @ [Wih_f|Wih_b]^T + bias ------------
__global__ void __launch_bounds__(256) xw_gemm(
        const int* __restrict__ documents, const int* __restrict__ querys,
        const float* __restrict__ emb,
        const float* __restrict__ Wf, const float* __restrict__ Wb,
        const float* __restrict__ bf, const float* __restrict__ bb)
{
    __shared__ float As[16*64];
    __shared__ float Bs[16*64];
    __shared__ int   toks[64];

    int tid = threadIdx.x;
    int r0  = blockIdx.y * 64;
    int n0  = blockIdx.x * 64;

    if (tid < 64) {
        int r = r0 + tid;
        toks[tid] = (r < NROW_DOC) ? documents[r] : querys[r - NROW_DOC];
    }
    __syncthreads();

    int tx = tid & 15;
    int ty = tid >> 4;
    int lrow = tid >> 2;
    int lkk  = (tid & 3) * 4;

    const float* arow = emb + (size_t)toks[lrow]*EDIM;
    const float* wrow;
    {
        int nG = n0 + lrow;
        wrow = (nG < G3H) ? (Wf + (size_t)nG*EDIM)
                          : (Wb + (size_t)(nG - G3H)*EDIM);
    }

    float c[4][4] = {};

    for (int k0 = 0; k0 < EDIM; k0 += 16) {
        float4 av = *(const float4*)(arow + k0 + lkk);
        float4 bv = *(const float4*)(wrow + k0 + lkk);
        As[(lkk+0)*64 + lrow] = av.x;
        As[(lkk+1)*64 + lrow] = av.y;
        As[(lkk+2)*64 + lrow] = av.z;
        As[(lkk+3)*64 + lrow] = av.w;
        Bs[(lkk+0)*64 + lrow] = bv.x;
        Bs[(lkk+1)*64 + lrow] = bv.y;
        Bs[(lkk+2)*64 + lrow] = bv.z;
        Bs[(lkk+3)*64 + lrow] = bv.w;
        __syncthreads();
        #pragma unroll
        for (int k = 0; k < 16; ++k) {
            float4 a4 = *(const float4*)&As[k*64 + ty*4];
            float4 b4 = *(const float4*)&Bs[k*64 + tx*4];
            float ar[4] = {a4.x, a4.y, a4.z, a4.w};
            float br[4] = {b4.x, b4.y, b4.z, b4.w};
            #pragma unroll
            for (int i = 0; i < 4; ++i)
                #pragma unroll
                for (int j = 0; j < 4; ++j)
                    c[i][j] += ar[i] * br[j];
        }
        __syncthreads();
    }

    int nbase = n0 + tx*4;
    float bias[4];
    #pragma unroll
    for (int j = 0; j < 4; ++j) {
        int nG = nbase + j;
        bias[j] = (nG < G3H) ? bf[nG] : bb[nG - G3H];
    }
    #pragma unroll
    for (int i = 0; i < 4; ++i) {
        int rG = r0 + ty*4 + i;
        float* dst = (rG < NROW_DOC)
            ? (g_xw_doc + (size_t)rG*1536 + nbase)
            : (g_xw_qry + (size_t)(rG - NROW_DOC)*1536 + nbase);
        float4 o = make_float4(c[i][0]+bias[0], c[i][1]+bias[1],
                               c[i][2]+bias[2], c[i][3]+bias[3]);
        *(float4*)dst = o;
    }
}

// ---------------- K2: GRU recurrence (2 batches x 1 dir per CTA) --------
__global__ void __launch_bounds__(768) gru_kernel(
        const int* __restrict__ lens,
        const float* __restrict__ bhh_f, const float* __restrict__ bhh_b,
        int T, int isQuery)
{
    __shared__ float hs[2*HDIM];       // interleaved hs[k*2+g]
    __shared__ float hhs[2*G3H];
    __shared__ int   lenS[2];

    int tid = threadIdx.x;
    int dir = blockIdx.y;
    int b0  = blockIdx.x * 2;

    const float* xw   = isQuery ? g_xw_qry : g_xw_doc;
    float*       hout = isQuery ? g_qry_h  : g_doc_h;
    const float* bhh  = dir ? bhh_b : bhh_f;

    if (tid < 2)        lenS[tid] = lens[b0 + tid];
    if (tid < 2*HDIM)   hs[tid] = 0.f;
    __syncthreads();
    int l0 = lenS[0], l1 = lenS[1];
    int Trun = (l0 > l1) ? l0 : l1;

    float bj = bhh[tid];
    const float4* wbase = ((const float4*)g_Wt) + (size_t)dir*64*G3H + tid;
    int g = tid >> 8;
    int i = tid & 255;

    for (int t = 0; t < Trun; ++t) {
        float acc0 = bj, acc1 = bj;
        const float4* wp = wbase;
        #pragma unroll 8
        for (int kc = 0; kc < 64; ++kc) {
            float4 w  = *wp; wp += G3H;
            float4 hA = *(const float4*)&hs[kc*8];
            float4 hB = *(const float4*)&hs[kc*8 + 4];
            acc0 += w.x*hA.x;  acc1 += w.x*hA.y;
            acc0 += w.y*hA.z;  acc1 += w.y*hA.w;
            acc0 += w.z*hB.x;  acc1 += w.z*hB.y;
            acc0 += w.w*hB.z;  acc1 += w.w*hB.w;
        }
        hhs[tid]       = acc0;
        hhs[G3H + tid] = acc1;
        __syncthreads();

        if (tid < 512) {
            int lg = (g == 0) ? l0 : l1;
            if (t < lg) {
                int tt = dir ? (lg - 1 - t) : t;
                int b  = b0 + g;
                const float* xr  = xw + ((size_t)b*T + tt)*1536 + dir*G3H;
                const float* hhg = hhs + g*G3H;
                float gr = xr[i]        + hhg[i];
                float gz = xr[HDIM+i]   + hhg[HDIM+i];
                float r  = 1.f/(1.f + expf(-gr));
                float z  = 1.f/(1.f + expf(-gz));
                float n  = tanhf(xr[2*HDIM+i] + r*hhg[2*HDIM+i]);
                float hp = hs[i*2 + g];
                float hn = (1.f - z)*n + z*hp;
                hs[i*2 + g] = hn;
                hout[((size_t)b*T + tt)*HH + dir*HDIM + i] = hn;
            }
        }
        __syncthreads();
    }

    // zero invalid tail so downstream scores are exactly 0 there (matches ref)
    if (tid < 512) {
        int lg = (g == 0) ? l0 : l1;
        int b  = b0 + g;
        for (int t2 = lg; t2 < T; ++t2)
            hout[((size_t)b*T + t2)*HH + dir*HDIM + i] = 0.f;
    }
}

// ---------------- K4: scores + softmaxes + s + probs --------------------
__device__ __forceinline__ float warpMax(float v) {
    #pragma unroll
    for (int o = 16; o > 0; o >>= 1)
        v = fmaxf(v, __shfl_xor_sync(0xffffffffu, v, o));
    return v;
}
__device__ __forceinline__ float warpSum(float v) {
    #pragma unroll
    for (int o = 16; o > 0; o >>= 1)
        v += __shfl_xor_sync(0xffffffffu, v, o);
    return v;
}

__global__ void __launch_bounds__(256) attn_kernel(
        const int* __restrict__ doc_lens, const int* __restrict__ qry_lens,
        const int* __restrict__ documents, const int* __restrict__ answers,
        float* __restrict__ out, int out_size)
{
    extern __shared__ float qht[];   // [512][32], bank = q -> conflict-free
    __shared__ float betasumW[8][32];
    __shared__ float colmaxW[8][32];
    __shared__ float colsumW[8][32];
    __shared__ float colmaxS[32];
    __shared__ float coefS[32];
    __shared__ float probW[8];

    int b    = blockIdx.x;
    int tid  = threadIdx.x;
    int lane = tid & 31;
    int w    = tid >> 5;
    int dlen = doc_lens[b];
    int qlen = qry_lens[b];
    int ans  = answers[b];

    for (int idx = tid; idx < TQRY*HH; idx += 256) {
        int q = idx >> 9;
        int c = idx & 511;
        qht[c*32 + q] = g_qry_h[((size_t)b*TQRY + q)*HH + c];
    }
    __syncthreads();

    float betasum = 0.f;
    float colmax  = -3.4e38f;
    float* scrow = g_scores + (size_t)b*TDOC*TQRY;
    const float* dhb = g_doc_h + (size_t)b*TDOC*HH;

    // pass 1: scores, beta row-softmax accumulation, unmasked colmax
    for (int it = 0; it < 32; ++it) {
        int d0 = w*128 + it*4;
        const float4* dr0 = (const float4*)(dhb + (size_t)(d0+0)*HH);
        const float4* dr1 = (const float4*)(dhb + (size_t)(d0+1)*HH);
        const float4* dr2 = (const float4*)(dhb + (size_t)(d0+2)*HH);
        const float4* dr3 = (const float4*)(dhb + (size_t)(d0+3)*HH);
        float s0=0.f, s1=0.f, s2=0.f, s3=0.f;
        #pragma unroll 4
        for (int c4 = 0; c4 < 128; ++c4) {
            float4 v0 = dr0[c4], v1 = dr1[c4], v2 = dr2[c4], v3 = dr3[c4];
            float q0 = qht[(c4*4+0)*32 + lane];
            float q1 = qht[(c4*4+1)*32 + lane];
            float q2 = qht[(c4*4+2)*32 + lane];
            float q3 = qht[(c4*4+3)*32 + lane];
            s0 += v0.x*q0 + v0.y*q1 + v0.z*q2 + v0.w*q3;
            s1 += v1.x*q0 + v1.y*q1 + v1.z*q2 + v1.w*q3;
            s2 += v2.x*q0 + v2.y*q1 + v2.z*q2 + v2.w*q3;
            s3 += v3.x*q0 + v3.y*q1 + v3.z*q2 + v3.w*q3;
        }
        float scs[4] = {s0, s1, s2, s3};
        #pragma unroll
        for (int r = 0; r < 4; ++r) {
            int d = d0 + r;
            float sc = scs[r];
            scrow[(size_t)d*TQRY + lane] = sc;
            colmax = fmaxf(colmax, sc);
            float mx = warpMax(sc);            // unmasked (matches reference)
            float mask = (d < dlen && lane < qlen) ? 1.f : 0.f;
            float e  = expf(sc - mx) * mask;
            float sm = warpSum(e);
            betasum += e / (sm + 1e-12f);
        }
    }
    betasumW[w][lane] = betasum;
    colmaxW[w][lane]  = colmax;
    __syncthreads();
    if (tid < 32) {
        float bs = 0.f, cm = -3.4e38f;
        #pragma unroll
        for (int ww = 0; ww < 8; ++ww) {
            bs += betasumW[ww][tid];
            cm = fmaxf(cm, colmaxW[ww][tid]);
        }
        colmaxS[tid] = cm;
        betasumW[0][tid] = bs;
    }
    __syncthreads();

    // pass 2: column sums for alpha
    float cmL = colmaxS[lane];
    float colsum = 0.f;
    for (int jr = 0; jr < 128; ++jr) {
        int d = w*128 + jr;
        float sc = scrow[(size_t)d*TQRY + lane];
        float mask = (d < dlen && lane < qlen) ? 1.f : 0.f;
        colsum += expf(sc - cmL) * mask;
    }
    colsumW[w][lane] = colsum;
    __syncthreads();
    if (tid < 32) {
        float cs = 0.f;
        #pragma unroll
        for (int ww = 0; ww < 8; ++ww) cs += colsumW[ww][tid];
        float beta_aver = betasumW[0][tid] / (float)dlen;
        coefS[tid] = beta_aver / (cs + 1e-12f);
    }
    __syncthreads();

    // pass 3: s[d] = sum_q alpha[d,q]*beta_aver[q]; probs
    float cf = coefS[lane];
    float prob = 0.f;
    for (int jr = 0; jr < 128; ++jr) {
        int d = w*128 + jr;
        float sc = scrow[(size_t)d*TQRY + lane];
        float mask = (d < dlen && lane < qlen) ? 1.f : 0.f;
        float sv = expf(sc - cmL) * mask * cf;
        sv = warpSum(sv);
        if (lane == 0) {
            g_s[b*TDOC + d] = sv;
            if (documents[b*TDOC + d] == ans) prob += sv;
        }
    }
    if (lane == 0) probW[w] = prob;
    __syncthreads();
    if (tid == 0) {
        float p = 0.f;
        #pragma unroll
        for (int ww = 0; ww < 8; ++ww) p += probW[ww];
        if (b < out_size) out[b] = p;
    }
}

// ---------------- word scores + argmax ----------------------------------
__global__ void word_init() {
    size_t idx = (size_t)blockIdx.x * blockDim.x + threadIdx.x;
    if (idx < (size_t)NB*VSZ) g_word[idx] = -1e30f;
}
__global__ void word_mark(const int* __restrict__ documents,
                          const int* __restrict__ doc_lens) {
    int idx = blockIdx.x * blockDim.x + threadIdx.x;
    int b = idx >> 10, d = idx & 1023;
    if (d < doc_lens[b]) g_word[(size_t)b*VSZ + documents[idx]] = 0.f;
}
__global__ void word_add(const int* __restrict__ documents,
                         const int* __restrict__ doc_lens) {
    int idx = blockIdx.x * blockDim.x + threadIdx.x;
    int b = idx >> 10, d = idx & 1023;
    if (d < doc_lens[b])
        atomicAdd(&g_word[(size_t)b*VSZ + documents[idx]], g_s[idx]);
}
__global__ void word_argmax(float* __restrict__ out, int out_size) {
    __shared__ float sv[256];
    __shared__ int   si[256];
    int b = blockIdx.x, tid = threadIdx.x;
    const float* wb = g_word + (size_t)b*VSZ;
    float best = -3.5e38f; int bi = 0;
    for (int v = tid; v < VSZ; v += 256) {
        float val = wb[v];
        if (val > best) { best = val; bi = v; }
    }
    sv[tid] = best; si[tid] = bi;
    __syncthreads();
    for (int s = 128; s > 0; s >>= 1) {
        if (tid < s) {
            if (sv[tid+s] > sv[tid] ||
                (sv[tid+s] == sv[tid] && si[tid+s] < si[tid])) {
                sv[tid] = sv[tid+s]; si[tid] = si[tid+s];
            }
        }
        __syncthreads();
    }
    if (tid == 0 && out_size >= NB + b + 1) out[NB + b] = (float)si[0];
}

// ---------------- launch -------------------------------------------------
extern "C" void kernel_launch(void* const* d_in, const int* in_sizes, int n_in,
                              void* d_out, int out_size) {
    const int*   documents = (const int*)  d_in[0];
    const int*   doc_lens  = (const int*)  d_in[1];
    const int*   querys    = (const int*)  d_in[2];
    const int*   query_lens= (const int*)  d_in[3];
    const int*   answers   = (const int*)  d_in[4];
    const float* emb       = (const float*)d_in[5];
    const float* Wih_f     = (const float*)d_in[6];
    const float* Whh_f     = (const float*)d_in[7];
    const float* bih_f     = (const float*)d_in[8];
    const float* bhh_f     = (const float*)d_in[9];
    const float* Wih_b     = (const float*)d_in[10];
    const float* Whh_b     = (const float*)d_in[11];
    const float* bih_b     = (const float*)d_in[12];
    const float* bhh_b     = (const float*)d_in[13];
    float* out = (float*)d_out;

    static bool attr_set = false;
    if (!attr_set) {
        cudaFuncSetAttribute(attn_kernel,
            cudaFuncAttributeMaxDynamicSharedMemorySize, 512*32*(int)sizeof(float));
        attr_set = true;
    }

    // K0: Whh transpose
    prep_wt<<<(2*HDIM*G3H + 255)/256, 256>>>(Whh_f, Whh_b);

    // K1: input projection GEMM for all doc+query tokens
    {
        dim3 grid(1536/64, (NROW_DOC + NROW_QRY)/64);
        xw_gemm<<<grid, 256>>>(documents, querys, emb,
                               Wih_f, Wih_b, bih_f, bih_b);
    }

    // K2: GRU recurrences (doc and query, both directions)
    {
        dim3 gridD(NB/2, 2);
        gru_kernel<<<gridD, 768>>>(doc_lens,   bhh_f, bhh_b, TDOC, 0);
        gru_kernel<<<gridD, 768>>>(query_lens, bhh_f, bhh_b, TQRY, 1);
    }

    // K4: attention + s + probs
    attn_kernel<<<NB, 256, 512*32*sizeof(float)>>>(
        doc_lens, query_lens, documents, answers, out, out_size);

    // word scores + argmax
    word_init<<<((size_t)NB*VSZ + 255)/256, 256>>>();
    word_mark<<<NROW_DOC/256, 256>>>(documents, doc_lens);
    word_add <<<NROW_DOC/256, 256>>>(documents, doc_lens);
    word_argmax<<<NB, 256>>>(out, out_size);
}

// round 10
// speedup vs baseline: 1.2447x; 1.2447x over previous
#include <cuda_runtime.h>
#include <math.h>
#include <stdint.h>

#define VSZ   50000
#define EDIM  384
#define HDIM  256
#define NB    64
#define TDOC  1024
#define TQRY  32
#define G3H   768
#define HH    512
#define NROW_DOC (NB*TDOC)
#define NROW_QRY (NB*TQRY)

#define CLS   8      // cluster size (j-slices of Whh)
#define GB    4      // batches per cluster
#define WROWS 96     // 768/8 rows per CTA
#define WPAD  260    // padded row stride (floats) -> conflict-free LDS.128

// ---------------- global scratch ----------------
__device__ float g_xw_doc[(size_t)NB*TDOC*1536];
__device__ float g_xw_qry[(size_t)NB*TQRY*1536];
__device__ float g_doc_h[(size_t)NB*TDOC*HH];
__device__ float g_qry_h[(size_t)NB*TQRY*HH];
__device__ float g_scores[(size_t)NB*TDOC*TQRY];
__device__ float g_s[NB*TDOC];
__device__ float g_word[(size_t)NB*VSZ];

__device__ __forceinline__ uint32_t smem_u32(const void* p) {
    return (uint32_t)__cvta_generic_to_shared(p);
}

// ---------------- zero hidden-state outputs (tails must be exact 0) -----
__global__ void zero_h() {
    size_t stride = (size_t)gridDim.x * blockDim.x;
    size_t i0 = (size_t)blockIdx.x * blockDim.x + threadIdx.x;
    float4 z = make_float4(0.f, 0.f, 0.f, 0.f);
    size_t nd = (size_t)NB*TDOC*HH/4;
    size_t nq = (size_t)NB*TQRY*HH/4;
    for (size_t k = i0; k < nd; k += stride) ((float4*)g_doc_h)[k] = z;
    for (size_t k = i0; k < nq; k += stride) ((float4*)g_qry_h)[k] = z;
}

// ---------------- K1: xw = emb[tok] @ [Wih_f|Wih_b]^T + bias ------------
__global__ void __launch_bounds__(256) xw_gemm(
        const int* __restrict__ documents, const int* __restrict__ querys,
        const float* __restrict__ emb,
        const float* __restrict__ Wf, const float* __restrict__ Wb,
        const float* __restrict__ bf, const float* __restrict__ bb)
{
    __shared__ float As[16*64];
    __shared__ float Bs[16*64];
    __shared__ int   toks[64];

    int tid = threadIdx.x;
    int r0  = blockIdx.y * 64;
    int n0  = blockIdx.x * 64;

    if (tid < 64) {
        int r = r0 + tid;
        toks[tid] = (r < NROW_DOC) ? documents[r] : querys[r - NROW_DOC];
    }
    __syncthreads();

    int tx = tid & 15;
    int ty = tid >> 4;
    int lrow = tid >> 2;
    int lkk  = (tid & 3) * 4;

    const float* arow = emb + (size_t)toks[lrow]*EDIM;
    const float* wrow;
    {
        int nG = n0 + lrow;
        wrow = (nG < G3H) ? (Wf + (size_t)nG*EDIM)
                          : (Wb + (size_t)(nG - G3H)*EDIM);
    }

    float c[4][4] = {};

    for (int k0 = 0; k0 < EDIM; k0 += 16) {
        float4 av = *(const float4*)(arow + k0 + lkk);
        float4 bv = *(const float4*)(wrow + k0 + lkk);
        As[(lkk+0)*64 + lrow] = av.x;
        As[(lkk+1)*64 + lrow] = av.y;
        As[(lkk+2)*64 + lrow] = av.z;
        As[(lkk+3)*64 + lrow] = av.w;
        Bs[(lkk+0)*64 + lrow] = bv.x;
        Bs[(lkk+1)*64 + lrow] = bv.y;
        Bs[(lkk+2)*64 + lrow] = bv.z;
        Bs[(lkk+3)*64 + lrow] = bv.w;
        __syncthreads();
        #pragma unroll
        for (int k = 0; k < 16; ++k) {
            float4 a4 = *(const float4*)&As[k*64 + ty*4];
            float4 b4 = *(const float4*)&Bs[k*64 + tx*4];
            float ar[4] = {a4.x, a4.y, a4.z, a4.w};
            float br[4] = {b4.x, b4.y, b4.z, b4.w};
            #pragma unroll
            for (int i = 0; i < 4; ++i)
                #pragma unroll
                for (int jj = 0; jj < 4; ++jj)
                    c[i][jj] += ar[i] * br[jj];
        }
        __syncthreads();
    }

    int nbase = n0 + tx*4;
    float bias[4];
    #pragma unroll
    for (int jj = 0; jj < 4; ++jj) {
        int nG = nbase + jj;
        bias[jj] = (nG < G3H) ? bf[nG] : bb[nG - G3H];
    }
    #pragma unroll
    for (int i = 0; i < 4; ++i) {
        int rG = r0 + ty*4 + i;
        float* dst = (rG < NROW_DOC)
            ? (g_xw_doc + (size_t)rG*1536 + nbase)
            : (g_xw_qry + (size_t)(rG - NROW_DOC)*1536 + nbase);
        float4 o = make_float4(c[i][0]+bias[0], c[i][1]+bias[1],
                               c[i][2]+bias[2], c[i][3]+bias[3]);
        *(float4*)dst = o;
    }
}

// ---------------- K2: cluster GRU, weights resident in SMEM --------------
// Cluster of 8 CTAs handles 4 batches x 1 dir.  CTA rank owns hidden units
// iG in [rank*32, rank*32+32): weight rows {iG, 256+iG, 512+iG} (96 rows).
// h (256 units x 4 batches) replicated in every CTA, ping-pong buffers;
// gate updates pushed to all 8 ranks via DSMEM; one cluster barrier/step.
__global__ void __launch_bounds__(384) __cluster_dims__(CLS, 1, 1)
gru_cluster(const int* __restrict__ lens,
            const float* __restrict__ Whh_f, const float* __restrict__ Whh_b,
            const float* __restrict__ bhh_f, const float* __restrict__ bhh_b,
            int T, int isQuery)
{
    extern __shared__ float dyn[];
    float* ws   = dyn;                    // [96][260]
    float* hbuf = dyn + WROWS*WPAD;       // 2 x 1024 floats: [kk][g][4] layout
    float* hh   = hbuf + 2048;            // [96][4]
    __shared__ int lenS[GB];

    int tid  = threadIdx.x;
    int rank = blockIdx.x & (CLS-1);
    int dir  = blockIdx.y;
    int b0   = (blockIdx.x >> 3) * GB;

    const float* xw   = isQuery ? g_xw_qry : g_xw_doc;
    float*       hout = isQuery ? g_qry_h  : g_doc_h;
    const float* W    = dir ? Whh_b : Whh_f;
    const float* bh   = dir ? bhh_b : bhh_f;

    if (tid < GB) lenS[tid] = lens[b0 + tid];

    // Load this CTA's 96 weight rows once (row j_local -> global row jg)
    for (int idx = tid; idx < WROWS*64; idx += 384) {
        int jr = idx >> 6, kk = idx & 63;
        int jgl = (jr >> 5)*256 + rank*32 + (jr & 31);
        *(float4*)&ws[jr*WPAD + kk*4] = *(const float4*)&W[(size_t)jgl*HDIM + kk*4];
    }
    for (int idx = tid; idx < 2048; idx += 384) hbuf[idx] = 0.f;
    __syncthreads();
    // all ranks' h buffers initialized before any peer can write them
    asm volatile("barrier.cluster.arrive.aligned;" ::: "memory");
    asm volatile("barrier.cluster.wait.aligned;"   ::: "memory");

    int l0 = lenS[0], l1 = lenS[1], l2 = lenS[2], l3 = lenS[3];
    int Trun = max(max(l0, l1), max(l2, l3));

    int j = tid >> 2;            // j_local 0..95  (dot phase)
    int g = tid & 3;             // batch in cluster
    int jg_row = (j >> 5)*256 + rank*32 + (j & 31);
    float bj = bh[jg_row];

    // gate-phase constants (threads 0..127: i_loc x g)
    int i_loc = tid >> 2;
    int iG    = rank*32 + i_loc;
    int lg    = lenS[g];
    int bb    = b0 + g;
    int hoff  = ((iG >> 2) * 16) + g*4 + (iG & 3);  // float idx in an h buffer

    uint32_t peer0[CLS], peer1[CLS];
    if (tid < 128) {
        uint32_t a0 = smem_u32(&hbuf[hoff]);
        uint32_t a1 = smem_u32(&hbuf[1024 + hoff]);
        #pragma unroll
        for (int r = 0; r < CLS; ++r) {
            asm("mapa.shared::cluster.u32 %0, %1, %2;" : "=r"(peer0[r]) : "r"(a0), "r"(r));
            asm("mapa.shared::cluster.u32 %0, %1, %2;" : "=r"(peer1[r]) : "r"(a1), "r"(r));
        }
    }

    int p = 0;
    for (int t = 0; t < Trun; ++t) {
        // prefetch xw gate inputs early (hidden under the dot phase)
        float xr_r = 0.f, xr_z = 0.f, xr_n = 0.f;
        int valid = 0;
        size_t obase = 0;
        if (tid < 128 && t < lg) {
            int tt = dir ? (lg - 1 - t) : t;
            const float* xp = xw + ((size_t)bb*T + tt)*1536 + dir*G3H;
            xr_r = xp[iG];
            xr_z = xp[HDIM + iG];
            xr_n = xp[2*HDIM + iG];
            obase = ((size_t)bb*T + tt)*HH + (size_t)dir*HDIM + iG;
            valid = 1;
        }

        // dot: hh[j,g] = bhh[jg] + sum_k Whh[jg][k] * h[k,g]
        const float4* wp4 = (const float4*)&ws[j*WPAD];
        const float4* hp4 = (const float4*)&hbuf[p*1024];
        float acc = bj;
        #pragma unroll 8
        for (int kk = 0; kk < 64; ++kk) {
            float4 w4 = wp4[kk];
            float4 h4 = hp4[kk*4 + g];
            acc += w4.x*h4.x; acc += w4.y*h4.y;
            acc += w4.z*h4.z; acc += w4.w*h4.w;
        }
        hh[tid] = acc;
        __syncthreads();

        if (tid < 128) {
            float hp = hbuf[p*1024 + hoff];
            float hn;
            if (valid) {
                float r_ = 1.f/(1.f + expf(-(xr_r + hh[i_loc*4      + g])));
                float z_ = 1.f/(1.f + expf(-(xr_z + hh[(32+i_loc)*4 + g])));
                float n_ = tanhf(xr_n + r_*hh[(64+i_loc)*4 + g]);
                hn = (1.f - z_)*n_ + z_*hp;
                hout[obase] = hn;
            } else {
                hn = hp;
            }
            const uint32_t* pa = (p ^ 1) ? peer1 : peer0;
            #pragma unroll
            for (int r = 0; r < CLS; ++r)
                asm volatile("st.shared::cluster.f32 [%0], %1;"
                             :: "r"(pa[r]), "f"(hn) : "memory");
        }
        // one barrier/step: h(t+1) visible everywhere; also block-wide sync
        asm volatile("barrier.cluster.arrive.aligned;" ::: "memory");
        asm volatile("barrier.cluster.wait.aligned;"   ::: "memory");
        p ^= 1;
    }
}

// ---------------- attention + softmaxes + s + probs ----------------------
__device__ __forceinline__ float warpMax(float v) {
    #pragma unroll
    for (int o = 16; o > 0; o >>= 1)
        v = fmaxf(v, __shfl_xor_sync(0xffffffffu, v, o));
    return v;
}
__device__ __forceinline__ float warpSum(float v) {
    #pragma unroll
    for (int o = 16; o > 0; o >>= 1)
        v += __shfl_xor_sync(0xffffffffu, v, o);
    return v;
}

__global__ void __launch_bounds__(256) attn_kernel(
        const int* __restrict__ doc_lens, const int* __restrict__ qry_lens,
        const int* __restrict__ documents, const int* __restrict__ answers,
        float* __restrict__ out, int out_size)
{
    extern __shared__ float qht[];   // [512][32], bank = q -> conflict-free
    __shared__ float betasumW[8][32];
    __shared__ float colmaxW[8][32];
    __shared__ float colsumW[8][32];
    __shared__ float colmaxS[32];
    __shared__ float coefS[32];
    __shared__ float probW[8];

    int b    = blockIdx.x;
    int tid  = threadIdx.x;
    int lane = tid & 31;
    int w    = tid >> 5;
    int dlen = doc_lens[b];
    int qlen = qry_lens[b];
    int ans  = answers[b];

    for (int idx = tid; idx < TQRY*HH; idx += 256) {
        int q = idx >> 9;
        int c = idx & 511;
        qht[c*32 + q] = g_qry_h[((size_t)b*TQRY + q)*HH + c];
    }
    __syncthreads();

    float betasum = 0.f;
    float colmax  = -3.4e38f;
    float* scrow = g_scores + (size_t)b*TDOC*TQRY;
    const float* dhb = g_doc_h + (size_t)b*TDOC*HH;

    for (int it = 0; it < 32; ++it) {
        int d0 = w*128 + it*4;
        const float4* dr0 = (const float4*)(dhb + (size_t)(d0+0)*HH);
        const float4* dr1 = (const float4*)(dhb + (size_t)(d0+1)*HH);
        const float4* dr2 = (const float4*)(dhb + (size_t)(d0+2)*HH);
        const float4* dr3 = (const float4*)(dhb + (size_t)(d0+3)*HH);
        float s0=0.f, s1=0.f, s2=0.f, s3=0.f;
        #pragma unroll 4
        for (int c4 = 0; c4 < 128; ++c4) {
            float4 v0 = dr0[c4], v1 = dr1[c4], v2 = dr2[c4], v3 = dr3[c4];
            float q0 = qht[(c4*4+0)*32 + lane];
            float q1 = qht[(c4*4+1)*32 + lane];
            float q2 = qht[(c4*4+2)*32 + lane];
            float q3 = qht[(c4*4+3)*32 + lane];
            s0 += v0.x*q0 + v0.y*q1 + v0.z*q2 + v0.w*q3;
            s1 += v1.x*q0 + v1.y*q1 + v1.z*q2 + v1.w*q3;
            s2 += v2.x*q0 + v2.y*q1 + v2.z*q2 + v2.w*q3;
            s3 += v3.x*q0 + v3.y*q1 + v3.z*q2 + v3.w*q3;
        }
        float scs[4] = {s0, s1, s2, s3};
        #pragma unroll
        for (int r = 0; r < 4; ++r) {
            int d = d0 + r;
            float sc = scs[r];
            scrow[(size_t)d*TQRY + lane] = sc;
            colmax = fmaxf(colmax, sc);
            float mx = warpMax(sc);            // unmasked (matches reference)
            float mask = (d < dlen && lane < qlen) ? 1.f : 0.f;
            float e  = expf(sc - mx) * mask;
            float sm = warpSum(e);
            betasum += e / (sm + 1e-12f);
        }
    }
    betasumW[w][lane] = betasum;
    colmaxW[w][lane]  = colmax;
    __syncthreads();
    if (tid < 32) {
        float bs = 0.f, cm = -3.4e38f;
        #pragma unroll
        for (int ww = 0; ww < 8; ++ww) {
            bs += betasumW[ww][tid];
            cm = fmaxf(cm, colmaxW[ww][tid]);
        }
        colmaxS[tid] = cm;
        betasumW[0][tid] = bs;
    }
    __syncthreads();

    float cmL = colmaxS[lane];
    float colsum = 0.f;
    for (int jr = 0; jr < 128; ++jr) {
        int d = w*128 + jr;
        float sc = scrow[(size_t)d*TQRY + lane];
        float mask = (d < dlen && lane < qlen) ? 1.f : 0.f;
        colsum += expf(sc - cmL) * mask;
    }
    colsumW[w][lane] = colsum;
    __syncthreads();
    if (tid < 32) {
        float cs = 0.f;
        #pragma unroll
        for (int ww = 0; ww < 8; ++ww) cs += colsumW[ww][tid];
        float beta_aver = betasumW[0][tid] / (float)dlen;
        coefS[tid] = beta_aver / (cs + 1e-12f);
    }
    __syncthreads();

    float cf = coefS[lane];
    float prob = 0.f;
    for (int jr = 0; jr < 128; ++jr) {
        int d = w*128 + jr;
        float sc = scrow[(size_t)d*TQRY + lane];
        float mask = (d < dlen && lane < qlen) ? 1.f : 0.f;
        float sv = expf(sc - cmL) * mask * cf;
        sv = warpSum(sv);
        if (lane == 0) {
            g_s[b*TDOC + d] = sv;
            if (documents[b*TDOC + d] == ans) prob += sv;
        }
    }
    if (lane == 0) probW[w] = prob;
    __syncthreads();
    if (tid == 0) {
        float p = 0.f;
        #pragma unroll
        for (int ww = 0; ww < 8; ++ww) p += probW[ww];
        if (b < out_size) out[b] = p;
    }
}

// ---------------- word scores + argmax ----------------------------------
__global__ void word_init() {
    size_t idx = (size_t)blockIdx.x * blockDim.x + threadIdx.x;
    if (idx < (size_t)NB*VSZ) g_word[idx] = -1e30f;
}
__global__ void word_mark(const int* __restrict__ documents,
                          const int* __restrict__ doc_lens) {
    int idx = blockIdx.x * blockDim.x + threadIdx.x;
    int b = idx >> 10, d = idx & 1023;
    if (d < doc_lens[b]) g_word[(size_t)b*VSZ + documents[idx]] = 0.f;
}
__global__ void word_add(const int* __restrict__ documents,
                         const int* __restrict__ doc_lens) {
    int idx = blockIdx.x * blockDim.x + threadIdx.x;
    int b = idx >> 10, d = idx & 1023;
    if (d < doc_lens[b])
        atomicAdd(&g_word[(size_t)b*VSZ + documents[idx]], g_s[idx]);
}
__global__ void word_argmax(float* __restrict__ out, int out_size) {
    __shared__ float sv[256];
    __shared__ int   si[256];
    int b = blockIdx.x, tid = threadIdx.x;
    const float* wb = g_word + (size_t)b*VSZ;
    float best = -3.5e38f; int bi = 0;
    for (int v = tid; v < VSZ; v += 256) {
        float val = wb[v];
        if (val > best) { best = val; bi = v; }
    }
    sv[tid] = best; si[tid] = bi;
    __syncthreads();
    for (int s = 128; s > 0; s >>= 1) {
        if (tid < s) {
            if (sv[tid+s] > sv[tid] ||
                (sv[tid+s] == sv[tid] && si[tid+s] < si[tid])) {
                sv[tid] = sv[tid+s]; si[tid] = si[tid+s];
            }
        }
        __syncthreads();
    }
    if (tid == 0 && out_size >= NB + b + 1) out[NB + b] = (float)si[0];
}

// ---------------- launch -------------------------------------------------
#define GRU_SMEM ((WROWS*WPAD + 2048 + 384) * (int)sizeof(float))

extern "C" void kernel_launch(void* const* d_in, const int* in_sizes, int n_in,
                              void* d_out, int out_size) {
    const int*   documents = (const int*)  d_in[0];
    const int*   doc_lens  = (const int*)  d_in[1];
    const int*   querys    = (const int*)  d_in[2];
    const int*   query_lens= (const int*)  d_in[3];
    const int*   answers   = (const int*)  d_in[4];
    const float* emb       = (const float*)d_in[5];
    const float* Wih_f     = (const float*)d_in[6];
    const float* Whh_f     = (const float*)d_in[7];
    const float* bih_f     = (const float*)d_in[8];
    const float* bhh_f     = (const float*)d_in[9];
    const float* Wih_b     = (const float*)d_in[10];
    const float* Whh_b     = (const float*)d_in[11];
    const float* bih_b     = (const float*)d_in[12];
    const float* bhh_b     = (const float*)d_in[13];
    float* out = (float*)d_out;

    static bool attr_set = false;
    if (!attr_set) {
        cudaFuncSetAttribute(attn_kernel,
            cudaFuncAttributeMaxDynamicSharedMemorySize, 512*32*(int)sizeof(float));
        cudaFuncSetAttribute(gru_cluster,
            cudaFuncAttributeMaxDynamicSharedMemorySize, GRU_SMEM);
        attr_set = true;
    }

    // zero hidden outputs (invalid tails must be exact 0)
    zero_h<<<2048, 256>>>();

    // input projection GEMM for all doc+query tokens
    {
        dim3 grid(1536/64, (NROW_DOC + NROW_QRY)/64);
        xw_gemm<<<grid, 256>>>(documents, querys, emb,
                               Wih_f, Wih_b, bih_f, bih_b);
    }

    // GRU recurrences: clusters of 8 CTAs, SMEM-resident weights
    {
        dim3 grid((NB/GB)*CLS, 2);   // (128, 2)
        gru_cluster<<<grid, 384, GRU_SMEM>>>(doc_lens, Whh_f, Whh_b,
                                             bhh_f, bhh_b, TDOC, 0);
        gru_cluster<<<grid, 384, GRU_SMEM>>>(query_lens, Whh_f, Whh_b,
                                             bhh_f, bhh_b, TQRY, 1);
    }

    // attention + s + probs
    attn_kernel<<<NB, 256, 512*32*sizeof(float)>>>(
        doc_lens, query_lens, documents, answers, out, out_size);

    // word scores + argmax
    word_init<<<((size_t)NB*VSZ + 255)/256, 256>>>();
    word_mark<<<NROW_DOC/256, 256>>>(documents, doc_lens);
    word_add <<<NROW_DOC/256, 256>>>(documents, doc_lens);
    word_argmax<<<NB, 256>>>(out, out_size);
}